// round 7
// baseline (speedup 1.0000x reference)
#include <cuda_runtime.h>
#include <cuda_bf16.h>
#include <cstdint>

#define SEQ_LEN 131072
#define NT      128
#define NCTA    296
#define THREADS 128
#define CHUNK   224          /* per chain; 592 chains cover 1..131071 */
#define WARM    8            /* exactly one tile */

__device__ double   g_gold[NCTA];
__device__ double   g_tot[NCTA];
__device__ unsigned g_done = 0;

__device__ __forceinline__ void cp16(void* dst_smem, const void* src) {
    unsigned d = (unsigned)__cvta_generic_to_shared(dst_smem);
    asm volatile("cp.async.cg.shared.global [%0], [%1], 16;" :: "r"(d), "l"(src));
}

// aligned-down base for the w2w staging window of a tile starting at tbase
__device__ __forceinline__ int w2w_albase(int tbase) {
    int a = tbase & ~3;                    // 16B-aligned element index
    if (a < 0) a = 0;
    if (a > SEQ_LEN - 12) a = SEQ_LEN - 12;
    return a;
}

// ---- emission/w2w tile prefetch for one chain: 8 steps = 4KB em + 48B w2w ----
__device__ __forceinline__ void tile_copy(const float* __restrict__ em,
                                          const int* __restrict__ w2w,
                                          int tbase, float* embuf, int* w2wbuf, int tid)
{
    int r = tid >> 4;            // row 0..7
    int c = tid & 15;            // 16B-chunk index
    int row = tbase + r;
    if (row < 0) row = 0;
    if (row > SEQ_LEN - 1) row = SEQ_LEN - 1;      // clamp: content unused past t_hi
    const float* src = em + (size_t)row * NT;
    cp16(embuf + r * NT + c * 4,      src + c * 4);
    cp16(embuf + r * NT + 64 + c * 4, src + 64 + c * 4);
    if (tid < 3) {               // 12 ints from 16B-aligned base (strictly aligned)
        int albase = w2w_albase(tbase);
        cp16(w2wbuf + tid * 4, w2w + albase + tid * 4);
    }
}

// ---- 128-length dot in bf16x2 (64 HFMA2), returns fp32 sum ----
__device__ __forceinline__ float dot_step(const __nv_bfloat162 (&k)[64],
                                          const __nv_bfloat162* __restrict__ vsrc)
{
    const uint4* vb = (const uint4*)vsrc;
    __nv_bfloat162 z = __float2bfloat162_rn(0.0f);
    __nv_bfloat162 acc[8] = {z, z, z, z, z, z, z, z};
    #pragma unroll
    for (int q = 0; q < 16; q++) {
        uint4 u = vb[q];
        acc[(4 * q + 0) & 7] = __hfma2(*(const __nv_bfloat162*)&u.x, k[4 * q + 0], acc[(4 * q + 0) & 7]);
        acc[(4 * q + 1) & 7] = __hfma2(*(const __nv_bfloat162*)&u.y, k[4 * q + 1], acc[(4 * q + 1) & 7]);
        acc[(4 * q + 2) & 7] = __hfma2(*(const __nv_bfloat162*)&u.z, k[4 * q + 2], acc[(4 * q + 2) & 7]);
        acc[(4 * q + 3) & 7] = __hfma2(*(const __nv_bfloat162*)&u.w, k[4 * q + 3], acc[(4 * q + 3) & 7]);
    }
    __nv_bfloat162 b0 = __hadd2(acc[0], acc[1]);
    __nv_bfloat162 b1 = __hadd2(acc[2], acc[3]);
    __nv_bfloat162 b2 = __hadd2(acc[4], acc[5]);
    __nv_bfloat162 b3 = __hadd2(acc[6], acc[7]);
    __nv_bfloat162 c0 = __hadd2(b0, b1);
    __nv_bfloat162 c1 = __hadd2(b2, b3);
    __nv_bfloat162 d  = __hadd2(c0, c1);
    return __low2float(d) + __high2float(d);
}

// ---- main kernel: gold + two interleaved warm-started chains per CTA ----
__global__ void __launch_bounds__(THREADS, 2)
crf_main(const float* __restrict__ em, const int* __restrict__ tags,
         const int* __restrict__ w2w, const float* __restrict__ trans_g,
         const float* __restrict__ trans_u2s, const float* __restrict__ trans_s2u,
         float* __restrict__ out)
{
    __shared__ __align__(16) __nv_bfloat16 vbufA[2][NT], vbufB[2][NT];
    __shared__ __align__(16) float embufA[2][8 * NT], embufB[2][8 * NT];
    __shared__ __align__(16) int   w2wbufA[2][12], w2wbufB[2][12];
    __shared__ float partialsA[4], partialsB[4];
    __shared__ float fpartA[4], fpartB[4];
    __shared__ double sgold[4];
    __shared__ int slast;

    const int tid  = threadIdx.x;
    const int cta  = blockIdx.x;
    const int lane = tid & 31;
    const int warp = tid >> 5;
    const int j    = tid;

    // ======== phase 1: gold path score (grid-stride, fp64, deterministic) ========
    double gacc = 0.0;
    for (int t = cta * THREADS + tid; t < SEQ_LEN; t += NCTA * THREADS) {
        int tcur = tags[t];
        gacc += (double)em[(size_t)t * NT + tcur];
        if (t >= 1) {
            int tprev = tags[t - 1];
            const float* tm = (w2w[t] == 0) ? trans_u2s : trans_s2u;
            gacc += (double)tm[tprev * NT + tcur];
        }
    }
    #pragma unroll
    for (int o = 16; o; o >>= 1) gacc += __shfl_down_sync(0xffffffffu, gacc, o);
    if (lane == 0) sgold[warp] = gacc;
    __syncthreads();
    if (tid == 0) g_gold[cta] = sgold[0] + sgold[1] + sgold[2] + sgold[3];

    // ======== phase 2: both K matrices' column j -> bf16x2 registers ========
    __nv_bfloat162 ka[64], kb[64];
    #pragma unroll
    for (int m = 0; m < 64; m++) {
        ka[m] = __floats2bfloat162_rn(__expf(trans_u2s[(2 * m) * NT + j]),
                                      __expf(trans_u2s[(2 * m + 1) * NT + j]));
        kb[m] = __floats2bfloat162_rn(__expf(trans_s2u[(2 * m) * NT + j]),
                                      __expf(trans_s2u[(2 * m + 1) * NT + j]));
    }

    // ======== phase 3: two interleaved chains ========
    const int cA = 2 * cta, cB = 2 * cta + 1;
    const int t_loA = 1 + cA * CHUNK,  t_loB = 1 + cB * CHUNK;
    const bool validA = t_loA < SEQ_LEN, validB = t_loB < SEQ_LEN;
    const int t_hiA = validA ? min(SEQ_LEN, t_loA + CHUNK) : 0;
    const int t_hiB = validB ? min(SEQ_LEN, t_loB + CHUNK) : 0;
    const int t0A = (cA == 0) ? 1 : (t_loA - WARM);
    const int t0B = t_loB - WARM;
    const int cfA = (cA == 0) ? 1 : 2;     // first counted tile entry
    const int cfB = 2;
    const int ntA = validA ? ((t_hiA - t0A + 7) >> 3) : 0;
    const int ntB = validB ? ((t_hiB - t0B + 7) >> 3) : 0;
    const int ntiles = max(ntA, ntB);

    vbufA[0][j] = (cA == 0) ? __float2bfloat16(__expf(em[j])) : __float2bfloat16(1.0f);
    vbufB[0][j] = __float2bfloat16(1.0f);

    tile_copy(em, w2w, t0A,     embufA[0], w2wbufA[0], tid);
    tile_copy(em, w2w, t0B,     embufB[0], w2wbufB[0], tid);
    asm volatile("cp.async.commit_group;" ::: "memory");
    tile_copy(em, w2w, t0A + 8, embufA[1], w2wbufA[1], tid);
    tile_copy(em, w2w, t0B + 8, embufB[1], w2wbufB[1], tid);
    asm volatile("cp.async.commit_group;" ::: "memory");

    double lamA = 0.0, lamB = 0.0;
    float  invA = 1.0f, invB = 1.0f;
    int    cur = 0;

    for (int k = 0; k < ntiles; k++) {
        asm volatile("cp.async.wait_group 1;" ::: "memory");
        __syncthreads();
        const int buf = k & 1;
        const int tbA = t0A + 8 * k;
        const int tbB = t0B + 8 * k;
        const int offA = tbA - w2w_albase(tbA);       // staging offset, 0..11
        const int offB = tbB - w2w_albase(tbB);

        if (k > 0) {  // lazy renorm bookkeeping (previous tile's end sums)
            float sA = partialsA[0] + partialsA[1] + partialsA[2] + partialsA[3];
            float sB = partialsB[0] + partialsB[1] + partialsB[2] + partialsB[3];
            if (k >= cfA && tbA < t_hiA) lamA += (double)logf(sA);
            if (k >= cfB && tbB < t_hiB) lamB += (double)logf(sB);
            invA = __fdividef(1.0f, sA);
            invB = __fdividef(1.0f, sB);
        }

        #pragma unroll
        for (int s = 0; s < 8; s++) {
            const int tA = tbA + s, tB = tbB + s;
            if (tA < t_hiA) {
                float ssum = (w2wbufA[buf][offA + s] == 0)
                               ? dot_step(ka, (const __nv_bfloat162*)&vbufA[cur][0])
                               : dot_step(kb, (const __nv_bfloat162*)&vbufA[cur][0]);
                float e = __expf(embufA[buf][s * NT + j]);
                float unew = e * ssum;
                if (s == 0) unew *= invA;
                vbufA[cur ^ 1][j] = __float2bfloat16(unew);
                if (s == 7 || tA == t_hiA - 1) {
                    float r = unew;
                    #pragma unroll
                    for (int o = 16; o; o >>= 1) r += __shfl_xor_sync(0xffffffffu, r, o);
                    if (lane == 0) {
                        if (s == 7)           partialsA[warp] = r;
                        if (tA == t_hiA - 1)  fpartA[warp] = r;
                    }
                }
            }
            if (tB < t_hiB) {
                float ssum = (w2wbufB[buf][offB + s] == 0)
                               ? dot_step(ka, (const __nv_bfloat162*)&vbufB[cur][0])
                               : dot_step(kb, (const __nv_bfloat162*)&vbufB[cur][0]);
                float e = __expf(embufB[buf][s * NT + j]);
                float unew = e * ssum;
                if (s == 0) unew *= invB;
                vbufB[cur ^ 1][j] = __float2bfloat16(unew);
                if (s == 7 || tB == t_hiB - 1) {
                    float r = unew;
                    #pragma unroll
                    for (int o = 16; o; o >>= 1) r += __shfl_xor_sync(0xffffffffu, r, o);
                    if (lane == 0) {
                        if (s == 7)           partialsB[warp] = r;
                        if (tB == t_hiB - 1)  fpartB[warp] = r;
                    }
                }
            }
            __syncthreads();
            cur ^= 1;
        }

        tile_copy(em, w2w, t0A + 8 * (k + 2), embufA[buf], w2wbufA[buf], tid);
        tile_copy(em, w2w, t0B + 8 * (k + 2), embufB[buf], w2wbufB[buf], tid);
        asm volatile("cp.async.commit_group;" ::: "memory");
    }
    __syncthreads();

    if (tid == 0) {
        double tot = 0.0;
        if (validA) tot += lamA + (double)logf(fpartA[0] + fpartA[1] + fpartA[2] + fpartA[3]);
        if (validB) tot += lamB + (double)logf(fpartB[0] + fpartB[1] + fpartB[2] + fpartB[3]);
        g_tot[cta] = tot;
        __threadfence();
        unsigned v = atomicAdd(&g_done, 1u);
        slast = (v == NCTA - 1) ? 1 : 0;
    }
    __syncthreads();

    // ======== fused finalize: unique last CTA sums partials (fixed order) ========
    if (slast) {
        __threadfence();                   // acquire: make other CTAs' g_tot visible
        double g = 0.0, t = 0.0;
        for (int i = tid; i < NCTA; i += THREADS) { g += g_gold[i]; t += g_tot[i]; }
        #pragma unroll
        for (int o = 16; o; o >>= 1) {
            g += __shfl_down_sync(0xffffffffu, g, o);
            t += __shfl_down_sync(0xffffffffu, t, o);
        }
        __shared__ double sg[4], st[4];
        if (lane == 0) { sg[warp] = g; st[warp] = t; }
        __syncthreads();
        if (tid == 0) {
            out[0] = (float)(sg[0] + sg[1] + sg[2] + sg[3]);
            out[1] = (float)(st[0] + st[1] + st[2] + st[3]);
            g_done = 0;                    // reset for next graph replay
        }
    }
}

extern "C" void kernel_launch(void* const* d_in, const int* in_sizes, int n_in,
                              void* d_out, int out_size) {
    const float* em   = (const float*)d_in[0];
    const int*   tags = (const int*)d_in[1];
    const int*   w2w  = (const int*)d_in[2];
    const float* tg   = (const float*)d_in[3];
    const float* tu2s = (const float*)d_in[4];
    const float* ts2u = (const float*)d_in[5];
    crf_main<<<NCTA, THREADS>>>(em, tags, w2w, tg, tu2s, ts2u, (float*)d_out);
}